// round 2
// baseline (speedup 1.0000x reference)
#include <cuda_runtime.h>
#include <math.h>
#include <stdint.h>

#define Bn 1024
#define Nn 512
#define En 256
#define Hn 128
#define An 32

// Scratch (device globals: no allocations allowed)
__device__ float g_xt[(size_t)Bn * Nn * Hn];   // 256 MB: x_t[b][n][h]
__device__ float g_d2[Bn * Hn];                // d2[b][h] = b1+b2+dec@W2

__device__ __forceinline__ float tanh_acc(float x) {
    float ax = fabsf(x);
    float e  = expf(-2.0f * ax);
    float r  = (1.0f - e) / (1.0f + e);
    return copysignf(r, x);
}

// ---------------------------------------------------------------------------
// Kernel 1: d2[b,h] = b1[h] + b2[h] + sum_k dec[b,k] * W2[k,h]
// ---------------------------------------------------------------------------
__global__ void k_d2(const float* __restrict__ dec, const float* __restrict__ W2,
                     const float* __restrict__ b1, const float* __restrict__ b2) {
    int b = blockIdx.x, h = threadIdx.x;
    __shared__ float ds[Hn];
    ds[h] = dec[b * Hn + h];
    __syncthreads();
    float acc = b1[h] + b2[h];
#pragma unroll 4
    for (int k = 0; k < Hn; k++) acc = fmaf(ds[k], W2[k * Hn + h], acc);
    g_d2[b * Hn + h] = acc;
}

// ---------------------------------------------------------------------------
// Kernel 2: x_t[b,n,h] = d2[b,h] + sum_e enc[b,e,n] * W1[e,h]
// 128n x 128h tile per CTA, K=256 in 16-chunks, 8x8 microtile, 256 threads.
// ---------------------------------------------------------------------------
__global__ void __launch_bounds__(256, 2)
k_encproj(const float* __restrict__ enc, const float* __restrict__ W1) {
    const int b = blockIdx.y;
    const int ntile = blockIdx.x << 7;
    const int t = threadIdx.x;
    const int tx = t & 15, ty = t >> 4;

    __shared__ float As[16][128];  // enc chunk [e][n]
    __shared__ float Bs[16][128];  // W1 chunk  [e][h]
    __shared__ float d2s[128];
    if (t < 128) d2s[t] = g_d2[b * Hn + t];

    const float* encb = enc + (size_t)b * En * Nn + ntile;

    float acc[8][8];
#pragma unroll
    for (int i = 0; i < 8; i++)
#pragma unroll
        for (int j = 0; j < 8; j++) acc[i][j] = 0.0f;

    const int e0 = t >> 5;          // 0..7
    const int q4 = (t & 31) << 2;   // 0..124

    float4 ra0 = *(const float4*)(encb + (size_t)e0 * Nn + q4);
    float4 ra1 = *(const float4*)(encb + (size_t)(e0 + 8) * Nn + q4);
    float4 rb0 = *(const float4*)(W1 + e0 * Hn + q4);
    float4 rb1 = *(const float4*)(W1 + (e0 + 8) * Hn + q4);

    for (int kc = 0; kc < 16; kc++) {
        __syncthreads();
        *(float4*)&As[e0][q4]     = ra0;
        *(float4*)&As[e0 + 8][q4] = ra1;
        *(float4*)&Bs[e0][q4]     = rb0;
        *(float4*)&Bs[e0 + 8][q4] = rb1;
        __syncthreads();
        if (kc < 15) {
            const float* ep = encb + (size_t)((kc + 1) * 16) * Nn;
            const float* wp = W1 + ((kc + 1) * 16) * Hn;
            ra0 = *(const float4*)(ep + (size_t)e0 * Nn + q4);
            ra1 = *(const float4*)(ep + (size_t)(e0 + 8) * Nn + q4);
            rb0 = *(const float4*)(wp + e0 * Hn + q4);
            rb1 = *(const float4*)(wp + (e0 + 8) * Hn + q4);
        }
#pragma unroll
        for (int k = 0; k < 16; k++) {
            float af[8], bf[8];
            *(float4*)&af[0] = *(float4*)&As[k][ty << 3];
            *(float4*)&af[4] = *(float4*)&As[k][(ty << 3) + 4];
            *(float4*)&bf[0] = *(float4*)&Bs[k][tx << 3];
            *(float4*)&bf[4] = *(float4*)&Bs[k][(tx << 3) + 4];
#pragma unroll
            for (int i = 0; i < 8; i++)
#pragma unroll
                for (int j = 0; j < 8; j++)
                    acc[i][j] = fmaf(af[i], bf[j], acc[i][j]);
        }
    }

    float* xrow = g_xt + ((size_t)b * Nn + ntile + (ty << 3)) * Hn + (tx << 3);
#pragma unroll
    for (int i = 0; i < 8; i++) {
        float4 v0, v1;
        v0.x = acc[i][0] + d2s[(tx << 3) + 0];
        v0.y = acc[i][1] + d2s[(tx << 3) + 1];
        v0.z = acc[i][2] + d2s[(tx << 3) + 2];
        v0.w = acc[i][3] + d2s[(tx << 3) + 3];
        v1.x = acc[i][4] + d2s[(tx << 3) + 4];
        v1.y = acc[i][5] + d2s[(tx << 3) + 5];
        v1.z = acc[i][6] + d2s[(tx << 3) + 6];
        v1.w = acc[i][7] + d2s[(tx << 3) + 7];
        *(float4*)(xrow + (size_t)i * Hn)     = v0;
        *(float4*)(xrow + (size_t)i * Hn + 4) = v1;
    }
}

// ---------------------------------------------------------------------------
// Kernel 3: everything else, one CTA (256 threads) per batch.
// Dynamic smem layout (floats):
//   Wbig  [16384]  : Wa (phase a) then Wwt (phase e)
//   tile  [64*132] : x_t n-tile, padded
//   u_s   [512], a_s [512], lg_s [512], c_s [128], cw_s [128], red [512]
// ---------------------------------------------------------------------------
#define SMEM3_FLOATS (16384 + 64 * 132 + 512 + 512 + 512 + 128 + 128 + 512)
#define SMEM3_BYTES  (SMEM3_FLOATS * 4)

__global__ void __launch_bounds__(256, 2)
k_batch(const float* __restrict__ dem,  const float* __restrict__ tload,
        const float* __restrict__ Wwt,  const float* __restrict__ bwt,
        const float* __restrict__ Wct,  const float* __restrict__ bct,
        const float* __restrict__ Wa,   const float* __restrict__ ba,
        const float* __restrict__ Va,   const float* __restrict__ bva,
        const float* __restrict__ Vc,   const float* __restrict__ bvc,
        const int*   __restrict__ capi, float* __restrict__ out) {
    const int b = blockIdx.x;
    const int t = threadIdx.x;
    extern __shared__ float sm[];
    float* Wbig = sm;                       // 16384
    float* tile = sm + 16384;               // 8448 (64 x 132)
    float* u_s  = tile + 64 * 132;          // 512
    float* a_s  = u_s + 512;                // 512
    float* lg_s = a_s + 512;                // 512
    float* c_s  = lg_s + 512;               // 128
    float* cw_s = c_s + 128;                // 128
    float* red  = cw_s + 128;               // 512 (2048B, 8B-aligned)

    const float* xtb = g_xt + (size_t)b * Nn * Hn;
    const float NEGINF = __int_as_float(0xff800000);

    // ---- phase a: u[n] = sum_a tanh(x_t[n]@Wa + ba)[a] * Va[a] + bva ----
    for (int i = t; i < Hn * An; i += 256) Wbig[i] = Wa[i];
    const int n4 = t >> 2;
    const int ag = (t & 3) << 3;
    float va_r[8], ba_r[8];
#pragma unroll
    for (int j = 0; j < 8; j++) { va_r[j] = Va[ag + j]; ba_r[j] = ba[ag + j]; }
    const float bva_r = bva[0];
    const float bvc_r = bvc[0];
    __syncthreads();

    for (int nt = 0; nt < 8; nt++) {
        for (int idx = t; idx < 2048; idx += 256) {
            int n = idx >> 5, q = idx & 31;
            *(float4*)&tile[n * 132 + (q << 2)] =
                *(const float4*)(xtb + (size_t)((nt << 6) + n) * Hn + (q << 2));
        }
        __syncthreads();
        float acc[8];
#pragma unroll
        for (int j = 0; j < 8; j++) acc[j] = ba_r[j];
        const float* trow = tile + n4 * 132;
#pragma unroll 4
        for (int h = 0; h < Hn; h++) {
            float x = trow[h];
            float4 w0 = *(const float4*)&Wbig[h * An + ag];
            float4 w1 = *(const float4*)&Wbig[h * An + ag + 4];
            acc[0] = fmaf(x, w0.x, acc[0]); acc[1] = fmaf(x, w0.y, acc[1]);
            acc[2] = fmaf(x, w0.z, acc[2]); acc[3] = fmaf(x, w0.w, acc[3]);
            acc[4] = fmaf(x, w1.x, acc[4]); acc[5] = fmaf(x, w1.y, acc[5]);
            acc[6] = fmaf(x, w1.z, acc[6]); acc[7] = fmaf(x, w1.w, acc[7]);
        }
        float s = 0.0f;
#pragma unroll
        for (int j = 0; j < 8; j++) s = fmaf(tanh_acc(acc[j]), va_r[j], s);
        s += __shfl_xor_sync(0xffffffffu, s, 1);
        s += __shfl_xor_sync(0xffffffffu, s, 2);
        if ((t & 3) == 0) u_s[(nt << 6) + n4] = s + bva_r;
        __syncthreads();
    }

    // kick off Wwt load into Wbig (consumed in phase e, after syncs below)
    for (int i = t; i < Hn * Hn; i += 256) Wbig[i] = Wwt[i];

    // ---- phase b: softmax(u) -> a_s ----
    float m = NEGINF;
    for (int n = t; n < Nn; n += 256) m = fmaxf(m, u_s[n]);
    red[t] = m; __syncthreads();
#pragma unroll
    for (int s = 128; s > 0; s >>= 1) {
        if (t < s) red[t] = fmaxf(red[t], red[t + s]);
        __syncthreads();
    }
    float mx = red[0]; __syncthreads();
    float ssum = 0.0f;
    for (int n = t; n < Nn; n += 256) {
        float e = expf(u_s[n] - mx);
        a_s[n] = e; ssum += e;
    }
    red[t] = ssum; __syncthreads();
#pragma unroll
    for (int s = 128; s > 0; s >>= 1) {
        if (t < s) red[t] += red[t + s];
        __syncthreads();
    }
    float inv = 1.0f / red[0]; __syncthreads();
    for (int n = t; n < Nn; n += 256) a_s[n] *= inv;
    __syncthreads();

    // ---- phase c: c_t[h] = sum_n a_t[n] * x_t[n,h] ----
    {
        int h = t & 127, piece = t >> 7;
        const float* xp = xtb + (size_t)piece * 256 * Hn + h;
        const float* ap = a_s + piece * 256;
        float c0 = 0.f, c1 = 0.f, c2 = 0.f, c3 = 0.f;
        for (int n = 0; n < 256; n += 4) {
            c0 = fmaf(ap[n + 0], xp[(size_t)(n + 0) * Hn], c0);
            c1 = fmaf(ap[n + 1], xp[(size_t)(n + 1) * Hn], c1);
            c2 = fmaf(ap[n + 2], xp[(size_t)(n + 2) * Hn], c2);
            c3 = fmaf(ap[n + 3], xp[(size_t)(n + 3) * Hn], c3);
        }
        red[t] = (c0 + c1) + (c2 + c3);
    }
    __syncthreads();
    if (t < 128) c_s[t] = red[t] + red[t + 128];
    __syncthreads();

    // ---- phase d: cw[h'] = bwt + bct + c_t @ Wct ----
    if (t < 128) {
        float acc = bwt[t] + bct[t];
#pragma unroll 4
        for (int h2 = 0; h2 < Hn; h2++) acc = fmaf(c_s[h2], Wct[h2 * Hn + t], acc);
        cw_s[t] = acc;
    }
    __syncthreads();

    // ---- phase e: logits[n] = tanh(x_t@Wwt + cw) @ Vc + bvc ----
    {
        const int tx = t & 15, ty = t >> 4;       // h' = 8*tx+j, n = 4*ty+i
        float vc_r[8];
#pragma unroll
        for (int j = 0; j < 8; j++) vc_r[j] = Vc[(tx << 3) + j];

        for (int nt = 0; nt < 8; nt++) {
            for (int idx = t; idx < 2048; idx += 256) {
                int n = idx >> 5, q = idx & 31;
                *(float4*)&tile[n * 132 + (q << 2)] =
                    *(const float4*)(xtb + (size_t)((nt << 6) + n) * Hn + (q << 2));
            }
            __syncthreads();
            float acc[4][8];
#pragma unroll
            for (int i = 0; i < 4; i++)
#pragma unroll
                for (int j = 0; j < 8; j++) acc[i][j] = cw_s[(tx << 3) + j];
#pragma unroll 2
            for (int k = 0; k < Hn; k++) {
                float bf[8];
                *(float4*)&bf[0] = *(const float4*)&Wbig[k * Hn + (tx << 3)];
                *(float4*)&bf[4] = *(const float4*)&Wbig[k * Hn + (tx << 3) + 4];
                float a0 = tile[((ty << 2) + 0) * 132 + k];
                float a1 = tile[((ty << 2) + 1) * 132 + k];
                float a2 = tile[((ty << 2) + 2) * 132 + k];
                float a3 = tile[((ty << 2) + 3) * 132 + k];
#pragma unroll
                for (int j = 0; j < 8; j++) {
                    acc[0][j] = fmaf(a0, bf[j], acc[0][j]);
                    acc[1][j] = fmaf(a1, bf[j], acc[1][j]);
                    acc[2][j] = fmaf(a2, bf[j], acc[2][j]);
                    acc[3][j] = fmaf(a3, bf[j], acc[3][j]);
                }
            }
#pragma unroll
            for (int i = 0; i < 4; i++) {
                float li = 0.0f;
#pragma unroll
                for (int j = 0; j < 8; j++) li = fmaf(tanh_acc(acc[i][j]), vc_r[j], li);
                li += __shfl_xor_sync(0xffffffffu, li, 1);
                li += __shfl_xor_sync(0xffffffffu, li, 2);
                li += __shfl_xor_sync(0xffffffffu, li, 4);
                li += __shfl_xor_sync(0xffffffffu, li, 8);
                if (tx == 0) lg_s[(nt << 6) + (ty << 2) + i] = li + bvc_r;
            }
            __syncthreads();
        }
    }

    // ---- phase f: log_softmax, mask, argmax, outputs ----
    float m2 = NEGINF;
    for (int n = t; n < Nn; n += 256) m2 = fmaxf(m2, lg_s[n]);
    red[t] = m2; __syncthreads();
#pragma unroll
    for (int s = 128; s > 0; s >>= 1) {
        if (t < s) red[t] = fmaxf(red[t], red[t + s]);
        __syncthreads();
    }
    float mx2 = red[0]; __syncthreads();
    float s2 = 0.0f;
    for (int n = t; n < Nn; n += 256) s2 += expf(lg_s[n] - mx2);
    red[t] = s2; __syncthreads();
#pragma unroll
    for (int s = 128; s > 0; s >>= 1) {
        if (t < s) red[t] += red[t + s];
        __syncthreads();
    }
    float lse = logf(red[0]); __syncthreads();

    const float loadv = tload[b];
    const bool  lz = (loadv == 0.0f);
    unsigned long long best = 0ull;
    for (int n = t; n < Nn; n += 256) {
        float d  = dem[(size_t)b * Nn + n];
        float lp = lg_s[n] - mx2 - lse;
        if (n > 0 && (d == 0.0f || lz)) lp = NEGINF;
        out[(size_t)b * Nn + n] = lp;
        unsigned ob = __float_as_uint(lp);
        ob = (ob & 0x80000000u) ? ~ob : (ob | 0x80000000u);
        unsigned long long key =
            ((unsigned long long)ob << 32) | (unsigned)(0xffffffffu - (unsigned)n);
        if (key > best) best = key;
    }
    unsigned long long* redu = (unsigned long long*)red;
    redu[t] = best; __syncthreads();
#pragma unroll
    for (int s = 128; s > 0; s >>= 1) {
        if (t < s && redu[t + s] > redu[t]) redu[t] = redu[t + s];
        __syncthreads();
    }
    __shared__ int   s_ptr;
    __shared__ float s_nds;
    if (t == 0) {
        unsigned long long k0 = redu[0];
        int ptr = (int)(0xffffffffu - (unsigned)(k0 & 0xffffffffu));
        float d_sel = dem[(size_t)b * Nn + ptr];
        float capf;
        if (capi) {
            int cv = *capi;
            capf = (cv > 0 && cv < 16777216) ? (float)cv : __int_as_float(cv);
        } else {
            capf = 1.0f;
        }
        float nl  = (ptr == 0) ? capf : (loadv - d_sel);
        float nds = (ptr == 0) ? d_sel : (d_sel - nl);
        out[(size_t)Bn * Nn + b]      = (float)ptr;
        out[(size_t)Bn * Nn + Bn + b] = nl;
        s_ptr = ptr; s_nds = nds;
    }
    __syncthreads();
    const int   ptr = s_ptr;
    const float nds = s_nds;
    float* outd = out + (size_t)Bn * Nn + 2 * Bn + (size_t)b * Nn;
    for (int n = t; n < Nn; n += 256) {
        float d = dem[(size_t)b * Nn + n];
        outd[n] = (n == ptr) ? nds : d;
    }
}

// ---------------------------------------------------------------------------
extern "C" void kernel_launch(void* const* d_in, const int* in_sizes, int n_in,
                              void* d_out, int out_size) {
    const float* dec  = (const float*)d_in[0];
    const float* enc  = (const float*)d_in[1];
    const float* tld  = (const float*)d_in[2];
    const float* dem  = (const float*)d_in[3];
    const float* W1   = (const float*)d_in[4];
    const float* b1   = (const float*)d_in[5];
    const float* W2   = (const float*)d_in[6];
    const float* b2   = (const float*)d_in[7];
    const float* Wwt  = (const float*)d_in[8];
    const float* bwt  = (const float*)d_in[9];
    const float* Wct  = (const float*)d_in[10];
    const float* bct  = (const float*)d_in[11];
    const float* Wa   = (const float*)d_in[12];
    const float* ba   = (const float*)d_in[13];
    const float* Va   = (const float*)d_in[14];
    const float* bva  = (const float*)d_in[15];
    const float* Vc   = (const float*)d_in[16];
    const float* bvc  = (const float*)d_in[17];
    const int*   cap  = (n_in >= 19) ? (const int*)d_in[18] : nullptr;
    float* out = (float*)d_out;
    (void)in_sizes; (void)out_size;

    static cudaError_t attr_rc =
        cudaFuncSetAttribute(k_batch, cudaFuncAttributeMaxDynamicSharedMemorySize,
                             SMEM3_BYTES);
    (void)attr_rc;

    k_d2<<<Bn, Hn>>>(dec, W2, b1, b2);
    k_encproj<<<dim3(Nn / 128, Bn), 256>>>(enc, W1);
    k_batch<<<Bn, 256, SMEM3_BYTES>>>(dem, tld, Wwt, bwt, Wct, bct,
                                      Wa, ba, Va, bva, Vc, bvc, cap, out);
}

// round 3
// speedup vs baseline: 1.0907x; 1.0907x over previous
#include <cuda_runtime.h>
#include <math.h>
#include <stdint.h>

#define Bn 1024
#define Nn 512
#define En 256
#define Hn 128
#define An 32

// Scratch (device globals: no allocations allowed)
__device__ float g_xt[(size_t)Bn * Nn * Hn];   // 256 MB: x_t[b][n][h]
__device__ float g_d2[Bn * Hn];                // d2[b][h] = b1+b2+dec@W2

typedef unsigned long long u64t;

// ---- packed fp32x2 helpers (Blackwell FFMA2 — PTX-only, IEEE per lane) ----
__device__ __forceinline__ void ffma2(u64t& d, u64t a, u64t b) {
    asm("fma.rn.f32x2 %0, %1, %2, %0;" : "+l"(d) : "l"(a), "l"(b));
}
__device__ __forceinline__ u64t fadd2(u64t a, u64t b) {
    u64t r; asm("add.rn.f32x2 %0, %1, %2;" : "=l"(r) : "l"(a), "l"(b)); return r;
}
__device__ __forceinline__ u64t pack2(float x, float y) {
    u64t r; asm("mov.b64 %0, {%1, %2};" : "=l"(r) : "f"(x), "f"(y)); return r;
}
__device__ __forceinline__ float2 unpack2(u64t v) {
    float2 f; asm("mov.b64 {%0, %1}, %2;" : "=f"(f.x), "=f"(f.y) : "l"(v)); return f;
}

__device__ __forceinline__ float tanh_acc(float x) {
    float ax = fabsf(x);
    float e  = expf(-2.0f * ax);
    float r  = __fdividef(1.0f - e, 1.0f + e);   // denom in [1,2]: well-conditioned
    return copysignf(r, x);
}

// ---------------------------------------------------------------------------
// Kernel 1: d2[b,h] = b1[h] + b2[h] + sum_k dec[b,k] * W2[k,h]
// ---------------------------------------------------------------------------
__global__ void k_d2(const float* __restrict__ dec, const float* __restrict__ W2,
                     const float* __restrict__ b1, const float* __restrict__ b2) {
    int b = blockIdx.x, h = threadIdx.x;
    __shared__ float ds[Hn];
    ds[h] = dec[b * Hn + h];
    __syncthreads();
    float acc = b1[h] + b2[h];
#pragma unroll 4
    for (int k = 0; k < Hn; k++) acc = fmaf(ds[k], W2[k * Hn + h], acc);
    g_d2[b * Hn + h] = acc;
}

// ---------------------------------------------------------------------------
// Kernel 2: x_t[b,n,h] = d2[b,h] + sum_e enc[b,e,n] * W1[e,h]
// 128n x 128h tile per CTA, K=256 in 16-chunks, 8x8 microtile via FFMA2.
// ---------------------------------------------------------------------------
__global__ void __launch_bounds__(256, 2)
k_encproj(const float* __restrict__ enc, const float* __restrict__ W1) {
    const int b = blockIdx.y;
    const int ntile = blockIdx.x << 7;
    const int t = threadIdx.x;
    const int tx = t & 15, ty = t >> 4;

    __shared__ float As[16][128];  // enc chunk [e][n]
    __shared__ float Bs[16][128];  // W1 chunk  [e][h]
    __shared__ float d2s[128];
    if (t < 128) d2s[t] = g_d2[b * Hn + t];

    const float* encb = enc + (size_t)b * En * Nn + ntile;

    u64t acc2[8][4];               // [n_i][h_pair]: 8 n x 8 h as 4 fp32x2 pairs
#pragma unroll
    for (int i = 0; i < 8; i++)
#pragma unroll
        for (int p = 0; p < 4; p++) acc2[i][p] = 0ull;

    const int e0 = t >> 5;          // 0..7
    const int q4 = (t & 31) << 2;   // 0..124

    float4 ra0 = *(const float4*)(encb + (size_t)e0 * Nn + q4);
    float4 ra1 = *(const float4*)(encb + (size_t)(e0 + 8) * Nn + q4);
    float4 rb0 = *(const float4*)(W1 + e0 * Hn + q4);
    float4 rb1 = *(const float4*)(W1 + (e0 + 8) * Hn + q4);

    for (int kc = 0; kc < 16; kc++) {
        __syncthreads();
        *(float4*)&As[e0][q4]     = ra0;
        *(float4*)&As[e0 + 8][q4] = ra1;
        *(float4*)&Bs[e0][q4]     = rb0;
        *(float4*)&Bs[e0 + 8][q4] = rb1;
        __syncthreads();
        if (kc < 15) {
            const float* ep = encb + (size_t)((kc + 1) * 16) * Nn;
            const float* wp = W1 + ((kc + 1) * 16) * Hn;
            ra0 = *(const float4*)(ep + (size_t)e0 * Nn + q4);
            ra1 = *(const float4*)(ep + (size_t)(e0 + 8) * Nn + q4);
            rb0 = *(const float4*)(wp + e0 * Hn + q4);
            rb1 = *(const float4*)(wp + (e0 + 8) * Hn + q4);
        }
#pragma unroll
        for (int k = 0; k < 16; k++) {
            float af[8];
            *(float4*)&af[0] = *(float4*)&As[k][ty << 3];
            *(float4*)&af[4] = *(float4*)&As[k][(ty << 3) + 4];
            ulonglong2 bp0 = *(const ulonglong2*)&Bs[k][tx << 3];
            ulonglong2 bp1 = *(const ulonglong2*)&Bs[k][(tx << 3) + 4];
#pragma unroll
            for (int i = 0; i < 8; i++) {
                u64t aa = pack2(af[i], af[i]);
                ffma2(acc2[i][0], aa, bp0.x);
                ffma2(acc2[i][1], aa, bp0.y);
                ffma2(acc2[i][2], aa, bp1.x);
                ffma2(acc2[i][3], aa, bp1.y);
            }
        }
    }

    // epilogue: + d2, store (packed adds + 128-bit stores)
    ulonglong2 d2p0 = *(const ulonglong2*)&d2s[tx << 3];
    ulonglong2 d2p1 = *(const ulonglong2*)&d2s[(tx << 3) + 4];
    float* xrow = g_xt + ((size_t)b * Nn + ntile + (ty << 3)) * Hn + (tx << 3);
#pragma unroll
    for (int i = 0; i < 8; i++) {
        ulonglong2 v0, v1;
        v0.x = fadd2(acc2[i][0], d2p0.x);
        v0.y = fadd2(acc2[i][1], d2p0.y);
        v1.x = fadd2(acc2[i][2], d2p1.x);
        v1.y = fadd2(acc2[i][3], d2p1.y);
        *(ulonglong2*)(xrow + (size_t)i * Hn)     = v0;
        *(ulonglong2*)(xrow + (size_t)i * Hn + 4) = v1;
    }
}

// ---------------------------------------------------------------------------
// Kernel 3: everything else, one CTA (256 threads) per batch.
// ---------------------------------------------------------------------------
#define SMEM3_FLOATS (16384 + 64 * 132 + 512 + 512 + 512 + 128 + 128 + 512)
#define SMEM3_BYTES  (SMEM3_FLOATS * 4)

__global__ void __launch_bounds__(256, 2)
k_batch(const float* __restrict__ dem,  const float* __restrict__ tload,
        const float* __restrict__ Wwt,  const float* __restrict__ bwt,
        const float* __restrict__ Wct,  const float* __restrict__ bct,
        const float* __restrict__ Wa,   const float* __restrict__ ba,
        const float* __restrict__ Va,   const float* __restrict__ bva,
        const float* __restrict__ Vc,   const float* __restrict__ bvc,
        const int*   __restrict__ capi, float* __restrict__ out) {
    const int b = blockIdx.x;
    const int t = threadIdx.x;
    extern __shared__ float sm[];
    float* Wbig = sm;                       // 16384
    float* tile = sm + 16384;               // 8448 (64 x 132)
    float* u_s  = tile + 64 * 132;          // 512
    float* a_s  = u_s + 512;                // 512
    float* lg_s = a_s + 512;                // 512
    float* c_s  = lg_s + 512;               // 128
    float* cw_s = c_s + 128;                // 128
    float* red  = cw_s + 128;               // 512

    const float* xtb = g_xt + (size_t)b * Nn * Hn;
    const float NEGINF = __int_as_float(0xff800000);

    // ---- phase a: u[n] = sum_a tanh(x_t[n]@Wa + ba)[a] * Va[a] + bva ----
    for (int i = t; i < Hn * An; i += 256) Wbig[i] = Wa[i];
    const int n4 = t >> 2;
    const int ag = (t & 3) << 3;
    float va_r[8];
    u64t bap[4];
    {
        ulonglong2 t0 = *(const ulonglong2*)&ba[ag];
        ulonglong2 t1 = *(const ulonglong2*)&ba[ag + 4];
        bap[0] = t0.x; bap[1] = t0.y; bap[2] = t1.x; bap[3] = t1.y;
    }
#pragma unroll
    for (int j = 0; j < 8; j++) va_r[j] = Va[ag + j];
    const float bva_r = bva[0];
    const float bvc_r = bvc[0];
    __syncthreads();

    for (int nt = 0; nt < 8; nt++) {
        for (int idx = t; idx < 2048; idx += 256) {
            int n = idx >> 5, q = idx & 31;
            *(float4*)&tile[n * 132 + (q << 2)] =
                *(const float4*)(xtb + (size_t)((nt << 6) + n) * Hn + (q << 2));
        }
        __syncthreads();
        u64t acc2[4];
#pragma unroll
        for (int p = 0; p < 4; p++) acc2[p] = bap[p];
        const float* trow = tile + n4 * 132;
#pragma unroll 4
        for (int h = 0; h < Hn; h++) {
            float x = trow[h];
            u64t xx = pack2(x, x);
            ulonglong2 w0 = *(const ulonglong2*)&Wbig[h * An + ag];
            ulonglong2 w1 = *(const ulonglong2*)&Wbig[h * An + ag + 4];
            ffma2(acc2[0], xx, w0.x);
            ffma2(acc2[1], xx, w0.y);
            ffma2(acc2[2], xx, w1.x);
            ffma2(acc2[3], xx, w1.y);
        }
        float s = 0.0f;
#pragma unroll
        for (int p = 0; p < 4; p++) {
            float2 v = unpack2(acc2[p]);
            s = fmaf(tanh_acc(v.x), va_r[2 * p],     s);
            s = fmaf(tanh_acc(v.y), va_r[2 * p + 1], s);
        }
        s += __shfl_xor_sync(0xffffffffu, s, 1);
        s += __shfl_xor_sync(0xffffffffu, s, 2);
        if ((t & 3) == 0) u_s[(nt << 6) + n4] = s + bva_r;
        __syncthreads();
    }

    // kick off Wwt load into Wbig (consumed in phase e, after syncs below)
    for (int i = t; i < Hn * Hn; i += 256) Wbig[i] = Wwt[i];

    // ---- phase b: softmax(u) -> a_s ----
    float m = NEGINF;
    for (int n = t; n < Nn; n += 256) m = fmaxf(m, u_s[n]);
    red[t] = m; __syncthreads();
#pragma unroll
    for (int s = 128; s > 0; s >>= 1) {
        if (t < s) red[t] = fmaxf(red[t], red[t + s]);
        __syncthreads();
    }
    float mx = red[0]; __syncthreads();
    float ssum = 0.0f;
    for (int n = t; n < Nn; n += 256) {
        float e = expf(u_s[n] - mx);
        a_s[n] = e; ssum += e;
    }
    red[t] = ssum; __syncthreads();
#pragma unroll
    for (int s = 128; s > 0; s >>= 1) {
        if (t < s) red[t] += red[t + s];
        __syncthreads();
    }
    float inv = 1.0f / red[0]; __syncthreads();
    for (int n = t; n < Nn; n += 256) a_s[n] *= inv;
    __syncthreads();

    // ---- phase c: c_t[h] = sum_n a_t[n] * x_t[n,h] ----
    {
        int h = t & 127, piece = t >> 7;
        const float* xp = xtb + (size_t)piece * 256 * Hn + h;
        const float* ap = a_s + piece * 256;
        float c0 = 0.f, c1 = 0.f, c2 = 0.f, c3 = 0.f;
        for (int n = 0; n < 256; n += 4) {
            c0 = fmaf(ap[n + 0], xp[(size_t)(n + 0) * Hn], c0);
            c1 = fmaf(ap[n + 1], xp[(size_t)(n + 1) * Hn], c1);
            c2 = fmaf(ap[n + 2], xp[(size_t)(n + 2) * Hn], c2);
            c3 = fmaf(ap[n + 3], xp[(size_t)(n + 3) * Hn], c3);
        }
        red[t] = (c0 + c1) + (c2 + c3);
    }
    __syncthreads();
    if (t < 128) c_s[t] = red[t] + red[t + 128];
    __syncthreads();

    // ---- phase d: cw[h'] = bwt + bct + c_t @ Wct ----
    if (t < 128) {
        float acc = bwt[t] + bct[t];
#pragma unroll 4
        for (int h2 = 0; h2 < Hn; h2++) acc = fmaf(c_s[h2], Wct[h2 * Hn + t], acc);
        cw_s[t] = acc;
    }
    __syncthreads();

    // ---- phase e: logits[n] = tanh(x_t@Wwt + cw) @ Vc + bvc ----
    {
        const int tx = t & 15, ty = t >> 4;       // h' = 8*tx+j, n = 4*ty+i
        float vc_r[8];
#pragma unroll
        for (int j = 0; j < 8; j++) vc_r[j] = Vc[(tx << 3) + j];
        ulonglong2 cw0 = *(const ulonglong2*)&cw_s[tx << 3];
        ulonglong2 cw1 = *(const ulonglong2*)&cw_s[(tx << 3) + 4];

        for (int nt = 0; nt < 8; nt++) {
            for (int idx = t; idx < 2048; idx += 256) {
                int n = idx >> 5, q = idx & 31;
                *(float4*)&tile[n * 132 + (q << 2)] =
                    *(const float4*)(xtb + (size_t)((nt << 6) + n) * Hn + (q << 2));
            }
            __syncthreads();
            u64t acc2[4][4];
#pragma unroll
            for (int i = 0; i < 4; i++) {
                acc2[i][0] = cw0.x; acc2[i][1] = cw0.y;
                acc2[i][2] = cw1.x; acc2[i][3] = cw1.y;
            }
#pragma unroll 2
            for (int k = 0; k < Hn; k++) {
                ulonglong2 bp0 = *(const ulonglong2*)&Wbig[k * Hn + (tx << 3)];
                ulonglong2 bp1 = *(const ulonglong2*)&Wbig[k * Hn + (tx << 3) + 4];
                float a0 = tile[((ty << 2) + 0) * 132 + k];
                float a1 = tile[((ty << 2) + 1) * 132 + k];
                float a2 = tile[((ty << 2) + 2) * 132 + k];
                float a3 = tile[((ty << 2) + 3) * 132 + k];
                u64t aa0 = pack2(a0, a0), aa1 = pack2(a1, a1);
                u64t aa2 = pack2(a2, a2), aa3 = pack2(a3, a3);
                ffma2(acc2[0][0], aa0, bp0.x); ffma2(acc2[0][1], aa0, bp0.y);
                ffma2(acc2[0][2], aa0, bp1.x); ffma2(acc2[0][3], aa0, bp1.y);
                ffma2(acc2[1][0], aa1, bp0.x); ffma2(acc2[1][1], aa1, bp0.y);
                ffma2(acc2[1][2], aa1, bp1.x); ffma2(acc2[1][3], aa1, bp1.y);
                ffma2(acc2[2][0], aa2, bp0.x); ffma2(acc2[2][1], aa2, bp0.y);
                ffma2(acc2[2][2], aa2, bp1.x); ffma2(acc2[2][3], aa2, bp1.y);
                ffma2(acc2[3][0], aa3, bp0.x); ffma2(acc2[3][1], aa3, bp0.y);
                ffma2(acc2[3][2], aa3, bp1.x); ffma2(acc2[3][3], aa3, bp1.y);
            }
#pragma unroll
            for (int i = 0; i < 4; i++) {
                float li = 0.0f;
#pragma unroll
                for (int p = 0; p < 4; p++) {
                    float2 v = unpack2(acc2[i][p]);
                    li = fmaf(tanh_acc(v.x), vc_r[2 * p],     li);
                    li = fmaf(tanh_acc(v.y), vc_r[2 * p + 1], li);
                }
                li += __shfl_xor_sync(0xffffffffu, li, 1);
                li += __shfl_xor_sync(0xffffffffu, li, 2);
                li += __shfl_xor_sync(0xffffffffu, li, 4);
                li += __shfl_xor_sync(0xffffffffu, li, 8);
                if (tx == 0) lg_s[(nt << 6) + (ty << 2) + i] = li + bvc_r;
            }
            __syncthreads();
        }
    }

    // ---- phase f: log_softmax, mask, argmax, outputs ----
    float m2 = NEGINF;
    for (int n = t; n < Nn; n += 256) m2 = fmaxf(m2, lg_s[n]);
    red[t] = m2; __syncthreads();
#pragma unroll
    for (int s = 128; s > 0; s >>= 1) {
        if (t < s) red[t] = fmaxf(red[t], red[t + s]);
        __syncthreads();
    }
    float mx2 = red[0]; __syncthreads();
    float s2 = 0.0f;
    for (int n = t; n < Nn; n += 256) s2 += expf(lg_s[n] - mx2);
    red[t] = s2; __syncthreads();
#pragma unroll
    for (int s = 128; s > 0; s >>= 1) {
        if (t < s) red[t] += red[t + s];
        __syncthreads();
    }
    float lse = logf(red[0]); __syncthreads();

    const float loadv = tload[b];
    const bool  lz = (loadv == 0.0f);
    unsigned long long best = 0ull;
    for (int n = t; n < Nn; n += 256) {
        float d  = dem[(size_t)b * Nn + n];
        float lp = lg_s[n] - mx2 - lse;
        if (n > 0 && (d == 0.0f || lz)) lp = NEGINF;
        out[(size_t)b * Nn + n] = lp;
        unsigned ob = __float_as_uint(lp);
        ob = (ob & 0x80000000u) ? ~ob : (ob | 0x80000000u);
        unsigned long long key =
            ((unsigned long long)ob << 32) | (unsigned)(0xffffffffu - (unsigned)n);
        if (key > best) best = key;
    }
    unsigned long long* redu = (unsigned long long*)red;
    redu[t] = best; __syncthreads();
#pragma unroll
    for (int s = 128; s > 0; s >>= 1) {
        if (t < s && redu[t + s] > redu[t]) redu[t] = redu[t + s];
        __syncthreads();
    }
    __shared__ int   s_ptr;
    __shared__ float s_nds;
    if (t == 0) {
        unsigned long long k0 = redu[0];
        int ptr = (int)(0xffffffffu - (unsigned)(k0 & 0xffffffffu));
        float d_sel = dem[(size_t)b * Nn + ptr];
        float capf;
        if (capi) {
            int cv = *capi;
            capf = (cv > 0 && cv < 16777216) ? (float)cv : __int_as_float(cv);
        } else {
            capf = 1.0f;
        }
        float nl  = (ptr == 0) ? capf : (loadv - d_sel);
        float nds = (ptr == 0) ? d_sel : (d_sel - nl);
        out[(size_t)Bn * Nn + b]      = (float)ptr;
        out[(size_t)Bn * Nn + Bn + b] = nl;
        s_ptr = ptr; s_nds = nds;
    }
    __syncthreads();
    const int   ptr = s_ptr;
    const float nds = s_nds;
    float* outd = out + (size_t)Bn * Nn + 2 * Bn + (size_t)b * Nn;
    for (int n = t; n < Nn; n += 256) {
        float d = dem[(size_t)b * Nn + n];
        outd[n] = (n == ptr) ? nds : d;
    }
}

// ---------------------------------------------------------------------------
extern "C" void kernel_launch(void* const* d_in, const int* in_sizes, int n_in,
                              void* d_out, int out_size) {
    const float* dec  = (const float*)d_in[0];
    const float* enc  = (const float*)d_in[1];
    const float* tld  = (const float*)d_in[2];
    const float* dem  = (const float*)d_in[3];
    const float* W1   = (const float*)d_in[4];
    const float* b1   = (const float*)d_in[5];
    const float* W2   = (const float*)d_in[6];
    const float* b2   = (const float*)d_in[7];
    const float* Wwt  = (const float*)d_in[8];
    const float* bwt  = (const float*)d_in[9];
    const float* Wct  = (const float*)d_in[10];
    const float* bct  = (const float*)d_in[11];
    const float* Wa   = (const float*)d_in[12];
    const float* ba   = (const float*)d_in[13];
    const float* Va   = (const float*)d_in[14];
    const float* bva  = (const float*)d_in[15];
    const float* Vc   = (const float*)d_in[16];
    const float* bvc  = (const float*)d_in[17];
    const int*   cap  = (n_in >= 19) ? (const int*)d_in[18] : nullptr;
    float* out = (float*)d_out;
    (void)in_sizes; (void)out_size;

    static cudaError_t attr_rc =
        cudaFuncSetAttribute(k_batch, cudaFuncAttributeMaxDynamicSharedMemorySize,
                             SMEM3_BYTES);
    (void)attr_rc;

    k_d2<<<Bn, Hn>>>(dec, W2, b1, b2);
    k_encproj<<<dim3(Nn / 128, Bn), 256>>>(enc, W1);
    k_batch<<<Bn, 256, SMEM3_BYTES>>>(dem, tld, Wwt, bwt, Wct, bct,
                                      Wa, ba, Va, bva, Vc, bvc, cap, out);
}